// round 3
// baseline (speedup 1.0000x reference)
#include <cuda_runtime.h>
#include <cuda_bf16.h>
#include <math.h>

#define VV   50000
#define VB   64
#define VS   512
#define VE   256
#define VH   512
#define VT   64
#define G3H  1536

typedef unsigned long long ull;

// ---------------------------------------------------------------------------
// Scratch (device globals; runtime allocation is forbidden)
// ---------------------------------------------------------------------------
__device__ float g_gi[(size_t)VS * VB * G3H];            // [s][b][3H]
// states slot 0 = h0(zeros); slot s+1 = h after step s.
// Layout per slot: [c=k/4][b][k%4]  (chunk-interleaved for coalescing)
__device__ float g_states[(size_t)(VS + 1) * VB * VH];
__device__ int g_tok[VB * VS];                            // int32 tokens [b][s]
__device__ unsigned g_bar_count;
__device__ unsigned g_bar_gen;

// ---------------------------------------------------------------------------
// f32x2 helpers
// ---------------------------------------------------------------------------
__device__ __forceinline__ ull fma2(ull a, ull b, ull c) {
    ull d;
    asm("fma.rn.f32x2 %0, %1, %2, %3;" : "=l"(d) : "l"(a), "l"(b), "l"(c));
    return d;
}
__device__ __forceinline__ ull pack2(float x, float y) {
    ull d;
    asm("mov.b64 %0, {%1, %2};" : "=l"(d) : "f"(x), "f"(y));
    return d;
}
__device__ __forceinline__ void unpk(ull a, float& x, float& y) {
    asm("mov.b64 {%0, %1}, %2;" : "=f"(x), "=f"(y) : "l"(a));
}
__device__ __forceinline__ float sum2(ull a) {
    float x, y; unpk(a, x, y); return x + y;
}
__device__ __forceinline__ void ldcg128(const void* p, ull& a, ull& b) {
    asm("ld.global.cg.v2.u64 {%0, %1}, [%2];" : "=l"(a), "=l"(b) : "l"(p));
}

// ---------------------------------------------------------------------------
// Token prologue: detect int32 vs int64 on device, convert+clamp into g_tok.
// int64 nonneg values < 2^31 have all-zero odd 32-bit words (little endian);
// for int32 data the odd words are uniform tokens — P(32 zeros) ~ 0.
// Single block so detection and conversion stay ordered.
// ---------------------------------------------------------------------------
__global__ void tok_kernel(const int* __restrict__ raw) {
    __shared__ int is64;
    const int tid = threadIdx.x;
    if (tid == 0) {
        int z = 1;
        for (int i = 0; i < 32; i++)
            if (raw[2 * i + 1] != 0) { z = 0; break; }
        is64 = z;
    }
    __syncthreads();
    const int stride = is64 ? 2 : 1;
    for (int i = tid; i < VB * VS; i += 256) {
        int t = raw[(size_t)i * stride];
        t = (t < 0) ? 0 : ((t >= VV) ? (VV - 1) : t);
        g_tok[i] = t;
    }
}

// ---------------------------------------------------------------------------
// Init: zero d_out, zero h0 slot, reset barrier (runs every replay)
// ---------------------------------------------------------------------------
__global__ void init_kernel(float* out, int out_size) {
    int i = blockIdx.x * blockDim.x + threadIdx.x;
    int stride = gridDim.x * blockDim.x;
    for (int j = i; j < out_size; j += stride) out[j] = 0.0f;
    for (int j = i; j < VB * VH; j += stride) g_states[j] = 0.0f;
    if (i == 0) { g_bar_count = 0u; g_bar_gen = 0u; }
}

// ---------------------------------------------------------------------------
// Kernel A: gi[s][b][:] = emb[tokens[b][s]] @ W_ih^T + b_ih
// M=32768 (m=s*64+b), N=1536, K=256. CTA tile 64x128, BK=32, micro 4x8.
// ---------------------------------------------------------------------------
__global__ void __launch_bounds__(256) gi_kernel(const float* __restrict__ emb,
                                                 const float* __restrict__ Wih,
                                                 const float* __restrict__ bih) {
    __shared__ __align__(16) float As[32 * 64];    // [k][m]
    __shared__ __align__(16) float Bs[32 * 128];   // [k][g]
    __shared__ int tok[64];

    const int tid = threadIdx.x;
    const int s = blockIdx.y;
    const int g0 = blockIdx.x * 128;

    if (tid < 64) tok[tid] = g_tok[tid * VS + s];

    const int rg = tid & 15;   // row group (4 rows)
    const int cg = tid >> 4;   // col group (8 cols)

    ull acc[4][4];
    {
        const float4 b0 = *(const float4*)&bih[g0 + cg * 8];
        const float4 b1 = *(const float4*)&bih[g0 + cg * 8 + 4];
        ull p0 = pack2(b0.x, b0.y), p1 = pack2(b0.z, b0.w);
        ull p2 = pack2(b1.x, b1.y), p3 = pack2(b1.z, b1.w);
#pragma unroll
        for (int i = 0; i < 4; i++) {
            acc[i][0] = p0; acc[i][1] = p1; acc[i][2] = p2; acc[i][3] = p3;
        }
    }
    __syncthreads();

    for (int kt = 0; kt < VE; kt += 32) {
        {   // stage A (gathered embedding rows) -> As[k][m]
            const int arow = tid >> 2, kq = tid & 3;
            const float* src = emb + (size_t)tok[arow] * VE + kt + kq * 8;
            const float4 v0 = *(const float4*)(src);
            const float4 v1 = *(const float4*)(src + 4);
            const int kb = kq * 8;
            As[(kb + 0) * 64 + arow] = v0.x; As[(kb + 1) * 64 + arow] = v0.y;
            As[(kb + 2) * 64 + arow] = v0.z; As[(kb + 3) * 64 + arow] = v0.w;
            As[(kb + 4) * 64 + arow] = v1.x; As[(kb + 5) * 64 + arow] = v1.y;
            As[(kb + 6) * 64 + arow] = v1.z; As[(kb + 7) * 64 + arow] = v1.w;
        }
        {   // stage B (W_ih rows g0..g0+127) -> Bs[k][g]
            const int grow = tid >> 1, kh = tid & 1;
            const float* src = Wih + (size_t)(g0 + grow) * VE + kt + kh * 16;
#pragma unroll
            for (int q = 0; q < 4; q++) {
                const float4 v = *(const float4*)(src + q * 4);
                const int kb = kh * 16 + q * 4;
                Bs[(kb + 0) * 128 + grow] = v.x; Bs[(kb + 1) * 128 + grow] = v.y;
                Bs[(kb + 2) * 128 + grow] = v.z; Bs[(kb + 3) * 128 + grow] = v.w;
            }
        }
        __syncthreads();
#pragma unroll
        for (int k = 0; k < 32; k++) {
            const float4 av = *(const float4*)&As[k * 64 + rg * 4];
            const ull pa0 = pack2(av.x, av.x), pa1 = pack2(av.y, av.y);
            const ull pa2 = pack2(av.z, av.z), pa3 = pack2(av.w, av.w);
            const ulonglong2 bA = *(const ulonglong2*)&Bs[k * 128 + cg * 8];
            const ulonglong2 bB = *(const ulonglong2*)&Bs[k * 128 + cg * 8 + 4];
            acc[0][0] = fma2(pa0, bA.x, acc[0][0]); acc[0][1] = fma2(pa0, bA.y, acc[0][1]);
            acc[0][2] = fma2(pa0, bB.x, acc[0][2]); acc[0][3] = fma2(pa0, bB.y, acc[0][3]);
            acc[1][0] = fma2(pa1, bA.x, acc[1][0]); acc[1][1] = fma2(pa1, bA.y, acc[1][1]);
            acc[1][2] = fma2(pa1, bB.x, acc[1][2]); acc[1][3] = fma2(pa1, bB.y, acc[1][3]);
            acc[2][0] = fma2(pa2, bA.x, acc[2][0]); acc[2][1] = fma2(pa2, bA.y, acc[2][1]);
            acc[2][2] = fma2(pa2, bB.x, acc[2][2]); acc[2][3] = fma2(pa2, bB.y, acc[2][3]);
            acc[3][0] = fma2(pa3, bA.x, acc[3][0]); acc[3][1] = fma2(pa3, bA.y, acc[3][1]);
            acc[3][2] = fma2(pa3, bB.x, acc[3][2]); acc[3][3] = fma2(pa3, bB.y, acc[3][3]);
        }
        __syncthreads();
    }

#pragma unroll
    for (int i = 0; i < 4; i++) {
        float o0, o1, o2, o3, o4, o5, o6, o7;
        unpk(acc[i][0], o0, o1); unpk(acc[i][1], o2, o3);
        unpk(acc[i][2], o4, o5); unpk(acc[i][3], o6, o7);
        float* dst = g_gi + (size_t)(s * VB + rg * 4 + i) * G3H + g0 + cg * 8;
        float4 w0; w0.x = o0; w0.y = o1; w0.z = o2; w0.w = o3;
        float4 w1; w1.x = o4; w1.y = o5; w1.z = o6; w1.w = o7;
        *(float4*)(dst) = w0;
        *(float4*)(dst + 4) = w1;
    }
}

// ---------------------------------------------------------------------------
// Kernel B: persistent GRU. 128 CTAs x 256 threads; CTA owns 4 hidden units.
// ---------------------------------------------------------------------------
#define GRU_CTAS 128
#define WPITCH   516   // pitch 2064B -> 4 distinct ul rows hit distinct banks

__global__ void __launch_bounds__(256, 1) gru_kernel(const float* __restrict__ Whh,
                                                     const float* __restrict__ bhh) {
    __shared__ __align__(16) float ws[12 * WPITCH];

    const int tid = threadIdx.x;
    const int cta = blockIdx.x;
    const int ul = tid & 3;     // unit within CTA (0..3)
    const int b  = tid >> 2;    // batch row (0..63)
    const int u  = cta * 4 + ul;

    // load this CTA's 12 W_hh rows (gate g, unit uu) -> local row g*4+uu
    for (int idx = tid; idx < 12 * VH; idx += 256) {
        const int lr = idx >> 9, k = idx & 511;
        const int g = lr >> 2, uu = lr & 3;
        ws[lr * WPITCH + k] = Whh[(size_t)(g * VH + cta * 4 + uu) * VH + k];
    }
    const float bR = bhh[u], bZ = bhh[VH + u], bN = bhh[2 * VH + u];
    __syncthreads();

    const ulonglong2* wR = (const ulonglong2*)&ws[(0 + ul) * WPITCH];
    const ulonglong2* wZ = (const ulonglong2*)&ws[(4 + ul) * WPITCH];
    const ulonglong2* wN = (const ulonglong2*)&ws[(8 + ul) * WPITCH];

    for (int s = 0; s < VS; s++) {
        const float* hf = g_states + (size_t)s * (VB * VH);
        ull ar0 = 0, ar1 = 0, az0 = 0, az1 = 0, an0 = 0, an1 = 0;
#pragma unroll 4
        for (int c = 0; c < 128; c++) {
            ull hx, hy;
            ldcg128((const char*)hf + (size_t)(c * 64 + b) * 16, hx, hy);
            const ulonglong2 r2 = wR[c];
            const ulonglong2 z2 = wZ[c];
            const ulonglong2 n2 = wN[c];
            ar0 = fma2(hx, r2.x, ar0); ar1 = fma2(hy, r2.y, ar1);
            az0 = fma2(hx, z2.x, az0); az1 = fma2(hy, z2.y, az1);
            an0 = fma2(hx, n2.x, an0); an1 = fma2(hy, n2.y, an1);
        }
        const float dr = sum2(ar0) + sum2(ar1);
        const float dz = sum2(az0) + sum2(az1);
        const float dn = sum2(an0) + sum2(an1);

        const float* gis = g_gi + (size_t)(s * VB + b) * G3H;
        const float gr = __ldg(gis + u);
        const float gz = __ldg(gis + VH + u);
        const float gn = __ldg(gis + 2 * VH + u);

        const float r = 1.0f / (1.0f + expf(-(gr + dr + bR)));
        const float z = 1.0f / (1.0f + expf(-(gz + dz + bZ)));
        const float n = tanhf(gn + r * (dn + bN));

        const float hp = __ldcg(hf + cta * 256 + tid);   // h_prev[b][u]
        const float hnew = (1.0f - z) * n + z * hp;

        __stcg(g_states + (size_t)(s + 1) * (VB * VH) + cta * 256 + tid, hnew);

        // grid-wide step barrier
        __syncthreads();
        if (tid == 0) {
            __threadfence();
            const unsigned arrived = atomicAdd(&g_bar_count, 1u);
            if (arrived == GRU_CTAS - 1) {
                atomicExch(&g_bar_count, 0u);
                __threadfence();
                atomicExch(&g_bar_gen, (unsigned)(s + 1));
            } else {
                while (*(volatile unsigned*)&g_bar_gen < (unsigned)(s + 1)) {}
            }
            __threadfence();
        }
        __syncthreads();
    }
}

// ---------------------------------------------------------------------------
// Kernel C: tag_logits = states @ W_tag^T + b_tag ; preds = first-argmax * mask
// CTA: 64 rows (m = b*512+s). W_tag staged in SMEM chunks of 128 k.
// ---------------------------------------------------------------------------
#define WT_PITCH 68

__global__ void __launch_bounds__(256) tag_kernel(const float* __restrict__ Wtag,
                                                  const float* __restrict__ btag,
                                                  float* __restrict__ out,
                                                  int preds_off, int write_preds) {
    __shared__ __align__(16) float Wt[128 * WT_PITCH];   // [k within chunk][tag]

    const int tid = threadIdx.x;
    const int r = tid >> 2;       // row within CTA (0..63)
    const int tg4 = tid & 3;      // tag quarter (16 tags)
    const int m = blockIdx.x * 64 + r;        // m = b*512 + s
    const int bb = m >> 9, s = m & 511;
    const float* st = g_states + (size_t)(s + 1) * (VB * VH) + bb * 4;

    float acc[16];
#pragma unroll
    for (int j = 0; j < 16; j++) acc[j] = btag[tg4 * 16 + j];

    for (int cc = 0; cc < 4; cc++) {
        __syncthreads();
        for (int idx = tid; idx < VT * 128; idx += 256) {
            const int tg = idx >> 7, kk = idx & 127;
            Wt[kk * WT_PITCH + tg] = Wtag[(size_t)tg * VH + cc * 128 + kk];
        }
        __syncthreads();
#pragma unroll 4
        for (int c = 0; c < 32; c++) {
            const float4 a4 = __ldg((const float4*)(st + (size_t)(cc * 32 + c) * 256));
#pragma unroll
            for (int kq = 0; kq < 4; kq++) {
                const float av = (kq == 0) ? a4.x : (kq == 1) ? a4.y : (kq == 2) ? a4.z : a4.w;
                const float4* w4p = (const float4*)&Wt[(c * 4 + kq) * WT_PITCH + tg4 * 16];
                const float4 w0 = w4p[0], w1 = w4p[1], w2 = w4p[2], w3 = w4p[3];
                acc[0]  = fmaf(av, w0.x, acc[0]);  acc[1]  = fmaf(av, w0.y, acc[1]);
                acc[2]  = fmaf(av, w0.z, acc[2]);  acc[3]  = fmaf(av, w0.w, acc[3]);
                acc[4]  = fmaf(av, w1.x, acc[4]);  acc[5]  = fmaf(av, w1.y, acc[5]);
                acc[6]  = fmaf(av, w1.z, acc[6]);  acc[7]  = fmaf(av, w1.w, acc[7]);
                acc[8]  = fmaf(av, w2.x, acc[8]);  acc[9]  = fmaf(av, w2.y, acc[9]);
                acc[10] = fmaf(av, w2.z, acc[10]); acc[11] = fmaf(av, w2.w, acc[11]);
                acc[12] = fmaf(av, w3.x, acc[12]); acc[13] = fmaf(av, w3.y, acc[13]);
                acc[14] = fmaf(av, w3.z, acc[14]); acc[15] = fmaf(av, w3.w, acc[15]);
            }
        }
    }

    // write logits
    {
        float* dst = out + (size_t)m * VT + tg4 * 16;
#pragma unroll
        for (int q = 0; q < 4; q++) {
            float4 v;
            v.x = acc[q * 4]; v.y = acc[q * 4 + 1];
            v.z = acc[q * 4 + 2]; v.w = acc[q * 4 + 3];
            *(float4*)(dst + q * 4) = v;
        }
    }

    if (write_preds) {
        // first-argmax over this thread's 16 tags (ascending j keeps first max)
        float v = acc[0]; int bi = 0;
#pragma unroll
        for (int j = 1; j < 16; j++) { if (acc[j] > v) { v = acc[j]; bi = j; } }
        bi += tg4 * 16;
        // combine across the 4-thread group; strictly-greater keeps the lower
        // index on ties (shuffle brings higher-index candidates), matching
        // jnp.argmax first-max semantics.
#pragma unroll
        for (int off = 2; off >= 1; off >>= 1) {
            const float v2 = __shfl_down_sync(0xFFFFFFFFu, v, off, 4);
            const int i2 = __shfl_down_sync(0xFFFFFFFFu, bi, off, 4);
            if (v2 > v) { v = v2; bi = i2; }
        }
        if (tg4 == 0) {
            const int t = g_tok[bb * VS + s];
            out[preds_off + m] = (t != 0) ? (float)bi : 0.0f;
        }
    }
}

// ---------------------------------------------------------------------------
extern "C" void kernel_launch(void* const* d_in, const int* in_sizes, int n_in,
                              void* d_out, int out_size) {
    const int*   tokens_raw = (const int*)d_in[0];
    const float* emb  = (const float*)d_in[1];
    const float* Wih  = (const float*)d_in[2];
    const float* Whh  = (const float*)d_in[3];
    const float* bih  = (const float*)d_in[4];
    const float* bhh  = (const float*)d_in[5];
    const float* Wtag = (const float*)d_in[6];
    const float* btag = (const float*)d_in[7];
    float* out = (float*)d_out;

    const int logits_n = VB * VS * VT;                 // 2097152
    const int write_preds = (out_size >= logits_n + VB * VS) ? 1 : 0;

    tok_kernel<<<1, 256>>>(tokens_raw);
    init_kernel<<<256, 256>>>(out, out_size);
    gi_kernel<<<dim3(12, 512), 256>>>(emb, Wih, bih);
    gru_kernel<<<GRU_CTAS, 256>>>(Whh, bhh);
    tag_kernel<<<512, 256>>>(Wtag, btag, out, logits_n, write_preds);
}

// round 5
// speedup vs baseline: 1.0987x; 1.0987x over previous
#include <cuda_runtime.h>
#include <cuda_bf16.h>
#include <math.h>

#define VV   50000
#define VB   64
#define VS   512
#define VE   256
#define VH   512
#define VT   64
#define G3H  1536

typedef unsigned long long ull;

// ---------------------------------------------------------------------------
// Scratch (device globals; runtime allocation is forbidden)
// ---------------------------------------------------------------------------
__device__ float g_gi[(size_t)VS * VB * G3H];            // [s][b][3H]
// states slot 0 = h0(zeros); slot s+1 = h after step s.
// Layout per slot: [c=k/4][b][k%4]  (chunk-interleaved, contiguous quarters)
__device__ float g_states[(size_t)(VS + 1) * VB * VH];
__device__ int g_tok[VB * VS];                            // int32 tokens [b][s]
__device__ unsigned g_bar_count;
__device__ unsigned g_bar_gen;

// ---------------------------------------------------------------------------
// f32x2 helpers
// ---------------------------------------------------------------------------
__device__ __forceinline__ ull fma2(ull a, ull b, ull c) {
    ull d;
    asm("fma.rn.f32x2 %0, %1, %2, %3;" : "=l"(d) : "l"(a), "l"(b), "l"(c));
    return d;
}
__device__ __forceinline__ ull pack2(float x, float y) {
    ull d;
    asm("mov.b64 %0, {%1, %2};" : "=l"(d) : "f"(x), "f"(y));
    return d;
}
__device__ __forceinline__ void unpk(ull a, float& x, float& y) {
    asm("mov.b64 {%0, %1}, %2;" : "=f"(x), "=f"(y) : "l"(a));
}
__device__ __forceinline__ float sum2(ull a) {
    float x, y; unpk(a, x, y); return x + y;
}

// ---------------------------------------------------------------------------
// Token prologue: detect int32 vs int64 on device, convert+clamp into g_tok.
// ---------------------------------------------------------------------------
__global__ void tok_kernel(const int* __restrict__ raw) {
    __shared__ int is64;
    const int tid = threadIdx.x;
    if (tid == 0) {
        int z = 1;
        for (int i = 0; i < 32; i++)
            if (raw[2 * i + 1] != 0) { z = 0; break; }
        is64 = z;
    }
    __syncthreads();
    const int stride = is64 ? 2 : 1;
    for (int i = tid; i < VB * VS; i += 256) {
        int t = raw[(size_t)i * stride];
        t = (t < 0) ? 0 : ((t >= VV) ? (VV - 1) : t);
        g_tok[i] = t;
    }
}

// ---------------------------------------------------------------------------
// Init: zero d_out, zero h0 slot, reset barrier (runs every replay)
// ---------------------------------------------------------------------------
__global__ void init_kernel(float* out, int out_size) {
    int i = blockIdx.x * blockDim.x + threadIdx.x;
    int stride = gridDim.x * blockDim.x;
    for (int j = i; j < out_size; j += stride) out[j] = 0.0f;
    for (int j = i; j < VB * VH; j += stride) g_states[j] = 0.0f;
    if (i == 0) { g_bar_count = 0u; g_bar_gen = 0u; }
}

// ---------------------------------------------------------------------------
// Kernel A: gi[s][b][:] = emb[tokens[b][s]] @ W_ih^T + b_ih   (R3-proven)
// ---------------------------------------------------------------------------
__global__ void __launch_bounds__(256) gi_kernel(const float* __restrict__ emb,
                                                 const float* __restrict__ Wih,
                                                 const float* __restrict__ bih) {
    __shared__ __align__(16) float As[32 * 64];    // [k][m]
    __shared__ __align__(16) float Bs[32 * 128];   // [k][g]
    __shared__ int tok[64];

    const int tid = threadIdx.x;
    const int s = blockIdx.y;
    const int g0 = blockIdx.x * 128;

    if (tid < 64) tok[tid] = g_tok[tid * VS + s];

    const int rg = tid & 15;
    const int cg = tid >> 4;

    ull acc[4][4];
    {
        const float4 b0 = *(const float4*)&bih[g0 + cg * 8];
        const float4 b1 = *(const float4*)&bih[g0 + cg * 8 + 4];
        ull p0 = pack2(b0.x, b0.y), p1 = pack2(b0.z, b0.w);
        ull p2 = pack2(b1.x, b1.y), p3 = pack2(b1.z, b1.w);
#pragma unroll
        for (int i = 0; i < 4; i++) {
            acc[i][0] = p0; acc[i][1] = p1; acc[i][2] = p2; acc[i][3] = p3;
        }
    }
    __syncthreads();

    for (int kt = 0; kt < VE; kt += 32) {
        {
            const int arow = tid >> 2, kq = tid & 3;
            const float* src = emb + (size_t)tok[arow] * VE + kt + kq * 8;
            const float4 v0 = *(const float4*)(src);
            const float4 v1 = *(const float4*)(src + 4);
            const int kb = kq * 8;
            As[(kb + 0) * 64 + arow] = v0.x; As[(kb + 1) * 64 + arow] = v0.y;
            As[(kb + 2) * 64 + arow] = v0.z; As[(kb + 3) * 64 + arow] = v0.w;
            As[(kb + 4) * 64 + arow] = v1.x; As[(kb + 5) * 64 + arow] = v1.y;
            As[(kb + 6) * 64 + arow] = v1.z; As[(kb + 7) * 64 + arow] = v1.w;
        }
        {
            const int grow = tid >> 1, kh = tid & 1;
            const float* src = Wih + (size_t)(g0 + grow) * VE + kt + kh * 16;
#pragma unroll
            for (int q = 0; q < 4; q++) {
                const float4 v = *(const float4*)(src + q * 4);
                const int kb = kh * 16 + q * 4;
                Bs[(kb + 0) * 128 + grow] = v.x; Bs[(kb + 1) * 128 + grow] = v.y;
                Bs[(kb + 2) * 128 + grow] = v.z; Bs[(kb + 3) * 128 + grow] = v.w;
            }
        }
        __syncthreads();
#pragma unroll
        for (int k = 0; k < 32; k++) {
            const float4 av = *(const float4*)&As[k * 64 + rg * 4];
            const ull pa0 = pack2(av.x, av.x), pa1 = pack2(av.y, av.y);
            const ull pa2 = pack2(av.z, av.z), pa3 = pack2(av.w, av.w);
            const ulonglong2 bA = *(const ulonglong2*)&Bs[k * 128 + cg * 8];
            const ulonglong2 bB = *(const ulonglong2*)&Bs[k * 128 + cg * 8 + 4];
            acc[0][0] = fma2(pa0, bA.x, acc[0][0]); acc[0][1] = fma2(pa0, bA.y, acc[0][1]);
            acc[0][2] = fma2(pa0, bB.x, acc[0][2]); acc[0][3] = fma2(pa0, bB.y, acc[0][3]);
            acc[1][0] = fma2(pa1, bA.x, acc[1][0]); acc[1][1] = fma2(pa1, bA.y, acc[1][1]);
            acc[1][2] = fma2(pa1, bB.x, acc[1][2]); acc[1][3] = fma2(pa1, bB.y, acc[1][3]);
            acc[2][0] = fma2(pa2, bA.x, acc[2][0]); acc[2][1] = fma2(pa2, bA.y, acc[2][1]);
            acc[2][2] = fma2(pa2, bB.x, acc[2][2]); acc[2][3] = fma2(pa2, bB.y, acc[2][3]);
            acc[3][0] = fma2(pa3, bA.x, acc[3][0]); acc[3][1] = fma2(pa3, bA.y, acc[3][1]);
            acc[3][2] = fma2(pa3, bB.x, acc[3][2]); acc[3][3] = fma2(pa3, bB.y, acc[3][3]);
        }
        __syncthreads();
    }

#pragma unroll
    for (int i = 0; i < 4; i++) {
        float o0, o1, o2, o3, o4, o5, o6, o7;
        unpk(acc[i][0], o0, o1); unpk(acc[i][1], o2, o3);
        unpk(acc[i][2], o4, o5); unpk(acc[i][3], o6, o7);
        float* dst = g_gi + (size_t)(s * VB + rg * 4 + i) * G3H + g0 + cg * 8;
        float4 w0; w0.x = o0; w0.y = o1; w0.z = o2; w0.w = o3;
        float4 w1; w1.x = o4; w1.y = o5; w1.z = o6; w1.w = o7;
        *(float4*)(dst) = w0;
        *(float4*)(dst + 4) = w1;
    }
}

// ---------------------------------------------------------------------------
// Kernel B: persistent GRU. cp.async stages h into FOUR distinct SMEM quarter
// buffers (no reuse within a step -> no WAR hazards). All copies issued up
// front; wait_group 3/2/1/0 gates each quarter's compute.
// ---------------------------------------------------------------------------
#define GRU_CTAS 128
#define WPITCH   516
#define QFLOATS  8192                      // quarter = 32 chunks x 64 b x 4 = 32KB
#define GRU_SMEM ((12 * WPITCH + 4 * QFLOATS) * 4)   // 155840 B

__device__ __forceinline__ void copy_q(float* sdst, const float* gsrc, int tid) {
    unsigned s0 = (unsigned)__cvta_generic_to_shared(sdst);
#pragma unroll
    for (int j = 0; j < 8; j++) {
        const int off = (j * 256 + tid) * 16;
        asm volatile("cp.async.cg.shared.global [%0], [%1], 16;"
                     :: "r"(s0 + off), "l"((const char*)gsrc + off) : "memory");
    }
    asm volatile("cp.async.commit_group;" ::: "memory");
}

__global__ void __launch_bounds__(256, 1) gru_kernel(const float* __restrict__ Whh,
                                                     const float* __restrict__ bhh) {
    extern __shared__ __align__(16) float dyn[];
    float* ws = dyn;                        // 12 * WPITCH
    float* hq[4];
    hq[0] = dyn + 12 * WPITCH;
    hq[1] = hq[0] + QFLOATS;
    hq[2] = hq[1] + QFLOATS;
    hq[3] = hq[2] + QFLOATS;

    const int tid = threadIdx.x;
    const int cta = blockIdx.x;
    const int ul = tid & 3;
    const int b  = tid >> 2;
    const int u  = cta * 4 + ul;

    for (int idx = tid; idx < 12 * VH; idx += 256) {
        const int lr = idx >> 9, k = idx & 511;
        const int g = lr >> 2, uu = lr & 3;
        ws[lr * WPITCH + k] = Whh[(size_t)(g * VH + cta * 4 + uu) * VH + k];
    }
    const float bR = bhh[u], bZ = bhh[VH + u], bN = bhh[2 * VH + u];
    __syncthreads();

    const ulonglong2* wR = (const ulonglong2*)&ws[(0 + ul) * WPITCH];
    const ulonglong2* wZ = (const ulonglong2*)&ws[(4 + ul) * WPITCH];
    const ulonglong2* wN = (const ulonglong2*)&ws[(8 + ul) * WPITCH];

#define COMPUTE(BUF, CG0)                                                   \
    {                                                                       \
        _Pragma("unroll 8")                                                 \
        for (int c = 0; c < 32; c++) {                                      \
            const ulonglong2 h2 = *(const ulonglong2*)((BUF) + (c * 64 + b) * 4); \
            const ulonglong2 r2 = wR[(CG0) + c];                            \
            const ulonglong2 z2 = wZ[(CG0) + c];                            \
            const ulonglong2 n2 = wN[(CG0) + c];                            \
            ar0 = fma2(h2.x, r2.x, ar0); ar1 = fma2(h2.y, r2.y, ar1);       \
            az0 = fma2(h2.x, z2.x, az0); az1 = fma2(h2.y, z2.y, az1);       \
            an0 = fma2(h2.x, n2.x, an0); an1 = fma2(h2.y, n2.y, an1);       \
        }                                                                   \
    }

    for (int s = 0; s < VS; s++) {
        const float* hf = g_states + (size_t)s * (VB * VH);

        // stage all four quarters up front (4 commit groups, max MLP)
        copy_q(hq[0], hf + 0 * QFLOATS, tid);
        copy_q(hq[1], hf + 1 * QFLOATS, tid);
        copy_q(hq[2], hf + 2 * QFLOATS, tid);
        copy_q(hq[3], hf + 3 * QFLOATS, tid);

        // early independent loads (consumed only in epilogue)
        const float* gis = g_gi + (size_t)(s * VB + b) * G3H;
        const float gr = __ldg(gis + u);
        const float gz = __ldg(gis + VH + u);
        const float gn = __ldg(gis + 2 * VH + u);
        const float hp = __ldcg(hf + cta * 256 + tid);

        ull ar0 = 0, ar1 = 0, az0 = 0, az1 = 0, an0 = 0, an1 = 0;

        asm volatile("cp.async.wait_group 3;" ::: "memory");
        __syncthreads();
        COMPUTE(hq[0], 0);
        asm volatile("cp.async.wait_group 2;" ::: "memory");
        __syncthreads();
        COMPUTE(hq[1], 32);
        asm volatile("cp.async.wait_group 1;" ::: "memory");
        __syncthreads();
        COMPUTE(hq[2], 64);
        asm volatile("cp.async.wait_group 0;" ::: "memory");
        __syncthreads();
        COMPUTE(hq[3], 96);

        const float dr = sum2(ar0) + sum2(ar1);
        const float dz = sum2(az0) + sum2(az1);
        const float dn = sum2(an0) + sum2(an1);

        const float r = 1.0f / (1.0f + expf(-(gr + dr + bR)));
        const float z = 1.0f / (1.0f + expf(-(gz + dz + bZ)));
        const float n = tanhf(gn + r * (dn + bN));
        const float hnew = (1.0f - z) * n + z * hp;

        __stcg(g_states + (size_t)(s + 1) * (VB * VH) + cta * 256 + tid, hnew);

        // grid-wide step barrier (R3-proven)
        __syncthreads();
        if (tid == 0) {
            __threadfence();
            const unsigned arrived = atomicAdd(&g_bar_count, 1u);
            if (arrived == GRU_CTAS - 1) {
                atomicExch(&g_bar_count, 0u);
                __threadfence();
                atomicExch(&g_bar_gen, (unsigned)(s + 1));
            } else {
                while (*(volatile unsigned*)&g_bar_gen < (unsigned)(s + 1)) {}
            }
            __threadfence();
        }
        __syncthreads();
    }
#undef COMPUTE
}

// ---------------------------------------------------------------------------
// Kernel C: tag_logits = states @ W_tag^T + b_tag ; preds (R3-proven)
// ---------------------------------------------------------------------------
#define WT_PITCH 68

__global__ void __launch_bounds__(256) tag_kernel(const float* __restrict__ Wtag,
                                                  const float* __restrict__ btag,
                                                  float* __restrict__ out,
                                                  int preds_off, int write_preds) {
    __shared__ __align__(16) float Wt[128 * WT_PITCH];

    const int tid = threadIdx.x;
    const int r = tid >> 2;
    const int tg4 = tid & 3;
    const int m = blockIdx.x * 64 + r;        // m = b*512 + s
    const int bb = m >> 9, s = m & 511;
    const float* st = g_states + (size_t)(s + 1) * (VB * VH) + bb * 4;

    float acc[16];
#pragma unroll
    for (int j = 0; j < 16; j++) acc[j] = btag[tg4 * 16 + j];

    for (int cc = 0; cc < 4; cc++) {
        __syncthreads();
        for (int idx = tid; idx < VT * 128; idx += 256) {
            const int tg = idx >> 7, kk = idx & 127;
            Wt[kk * WT_PITCH + tg] = Wtag[(size_t)tg * VH + cc * 128 + kk];
        }
        __syncthreads();
#pragma unroll 4
        for (int c = 0; c < 32; c++) {
            const float4 a4 = __ldg((const float4*)(st + (size_t)(cc * 32 + c) * 256));
#pragma unroll
            for (int kq = 0; kq < 4; kq++) {
                const float av = (kq == 0) ? a4.x : (kq == 1) ? a4.y : (kq == 2) ? a4.z : a4.w;
                const float4* w4p = (const float4*)&Wt[(c * 4 + kq) * WT_PITCH + tg4 * 16];
                const float4 w0 = w4p[0], w1 = w4p[1], w2 = w4p[2], w3 = w4p[3];
                acc[0]  = fmaf(av, w0.x, acc[0]);  acc[1]  = fmaf(av, w0.y, acc[1]);
                acc[2]  = fmaf(av, w0.z, acc[2]);  acc[3]  = fmaf(av, w0.w, acc[3]);
                acc[4]  = fmaf(av, w1.x, acc[4]);  acc[5]  = fmaf(av, w1.y, acc[5]);
                acc[6]  = fmaf(av, w1.z, acc[6]);  acc[7]  = fmaf(av, w1.w, acc[7]);
                acc[8]  = fmaf(av, w2.x, acc[8]);  acc[9]  = fmaf(av, w2.y, acc[9]);
                acc[10] = fmaf(av, w2.z, acc[10]); acc[11] = fmaf(av, w2.w, acc[11]);
                acc[12] = fmaf(av, w3.x, acc[12]); acc[13] = fmaf(av, w3.y, acc[13]);
                acc[14] = fmaf(av, w3.z, acc[14]); acc[15] = fmaf(av, w3.w, acc[15]);
            }
        }
    }

    {
        float* dst = out + (size_t)m * VT + tg4 * 16;
#pragma unroll
        for (int q = 0; q < 4; q++) {
            float4 v;
            v.x = acc[q * 4]; v.y = acc[q * 4 + 1];
            v.z = acc[q * 4 + 2]; v.w = acc[q * 4 + 3];
            *(float4*)(dst + q * 4) = v;
        }
    }

    if (write_preds) {
        float v = acc[0]; int bi = 0;
#pragma unroll
        for (int j = 1; j < 16; j++) { if (acc[j] > v) { v = acc[j]; bi = j; } }
        bi += tg4 * 16;
#pragma unroll
        for (int off = 2; off >= 1; off >>= 1) {
            const float v2 = __shfl_down_sync(0xFFFFFFFFu, v, off, 4);
            const int i2 = __shfl_down_sync(0xFFFFFFFFu, bi, off, 4);
            if (v2 > v) { v = v2; bi = i2; }
        }
        if (tg4 == 0) {
            const int t = g_tok[bb * VS + s];
            out[preds_off + m] = (t != 0) ? (float)bi : 0.0f;
        }
    }
}

// ---------------------------------------------------------------------------
extern "C" void kernel_launch(void* const* d_in, const int* in_sizes, int n_in,
                              void* d_out, int out_size) {
    const int*   tokens_raw = (const int*)d_in[0];
    const float* emb  = (const float*)d_in[1];
    const float* Wih  = (const float*)d_in[2];
    const float* Whh  = (const float*)d_in[3];
    const float* bih  = (const float*)d_in[4];
    const float* bhh  = (const float*)d_in[5];
    const float* Wtag = (const float*)d_in[6];
    const float* btag = (const float*)d_in[7];
    float* out = (float*)d_out;

    const int logits_n = VB * VS * VT;                 // 2097152
    const int write_preds = (out_size >= logits_n + VB * VS) ? 1 : 0;

    static int smem_set = 0;
    if (!smem_set) {
        cudaFuncSetAttribute(gru_kernel, cudaFuncAttributeMaxDynamicSharedMemorySize, GRU_SMEM);
        smem_set = 1;
    }

    tok_kernel<<<1, 256>>>(tokens_raw);
    init_kernel<<<256, 256>>>(out, out_size);
    gi_kernel<<<dim3(12, 512), 256>>>(emb, Wih, bih);
    gru_kernel<<<GRU_CTAS, 256, GRU_SMEM>>>(Whh, bhh);
    tag_kernel<<<512, 256>>>(Wtag, btag, out, logits_n, write_preds);
}

// round 6
// speedup vs baseline: 1.7156x; 1.5614x over previous
#include <cuda_runtime.h>
#include <cuda_bf16.h>
#include <math.h>

#define VV   50000
#define VB   64
#define VS   512
#define VE   256
#define VH   512
#define VT   64
#define G3H  1536

typedef unsigned long long ull;

// ---------------------------------------------------------------------------
// Scratch (device globals; runtime allocation is forbidden)
// ---------------------------------------------------------------------------
__device__ float g_gi[(size_t)VS * VB * G3H];            // [s][b][3H]
// states slot 0 = h0(zeros); slot s+1 = h after step s.
// Layout per slot: [c=k/4][b][k%4]  (chunk-interleaved, contiguous quarters)
__device__ float g_states[(size_t)(VS + 1) * VB * VH];
__device__ int g_tok[VB * VS];                            // int32 tokens [b][s]
__device__ unsigned g_bar_count;
__device__ unsigned g_bar_gen;

// ---------------------------------------------------------------------------
// f32x2 helpers
// ---------------------------------------------------------------------------
__device__ __forceinline__ ull fma2(ull a, ull b, ull c) {
    ull d;
    asm("fma.rn.f32x2 %0, %1, %2, %3;" : "=l"(d) : "l"(a), "l"(b), "l"(c));
    return d;
}
__device__ __forceinline__ ull pack2(float x, float y) {
    ull d;
    asm("mov.b64 %0, {%1, %2};" : "=l"(d) : "f"(x), "f"(y));
    return d;
}
__device__ __forceinline__ void unpk(ull a, float& x, float& y) {
    asm("mov.b64 {%0, %1}, %2;" : "=f"(x), "=f"(y) : "l"(a));
}
__device__ __forceinline__ float sum2(ull a) {
    float x, y; unpk(a, x, y); return x + y;
}

// ---------------------------------------------------------------------------
// Token prologue: detect int32 vs int64 on device, convert+clamp into g_tok.
// ---------------------------------------------------------------------------
__global__ void tok_kernel(const int* __restrict__ raw) {
    __shared__ int is64;
    const int tid = threadIdx.x;
    if (tid == 0) {
        int z = 1;
        for (int i = 0; i < 32; i++)
            if (raw[2 * i + 1] != 0) { z = 0; break; }
        is64 = z;
    }
    __syncthreads();
    const int stride = is64 ? 2 : 1;
    for (int i = tid; i < VB * VS; i += 256) {
        int t = raw[(size_t)i * stride];
        t = (t < 0) ? 0 : ((t >= VV) ? (VV - 1) : t);
        g_tok[i] = t;
    }
}

// ---------------------------------------------------------------------------
// Init: zero d_out, zero h0 slot, reset barrier (runs every replay)
// ---------------------------------------------------------------------------
__global__ void init_kernel(float* out, int out_size) {
    int i = blockIdx.x * blockDim.x + threadIdx.x;
    int stride = gridDim.x * blockDim.x;
    for (int j = i; j < out_size; j += stride) out[j] = 0.0f;
    for (int j = i; j < VB * VH; j += stride) g_states[j] = 0.0f;
    if (i == 0) { g_bar_count = 0u; g_bar_gen = 0u; }
}

// ---------------------------------------------------------------------------
// Kernel A: gi[s][b][:] = emb[tokens[b][s]] @ W_ih^T + b_ih   (proven)
// ---------------------------------------------------------------------------
__global__ void __launch_bounds__(256) gi_kernel(const float* __restrict__ emb,
                                                 const float* __restrict__ Wih,
                                                 const float* __restrict__ bih) {
    __shared__ __align__(16) float As[32 * 64];    // [k][m]
    __shared__ __align__(16) float Bs[32 * 128];   // [k][g]
    __shared__ int tok[64];

    const int tid = threadIdx.x;
    const int s = blockIdx.y;
    const int g0 = blockIdx.x * 128;

    if (tid < 64) tok[tid] = g_tok[tid * VS + s];

    const int rg = tid & 15;
    const int cg = tid >> 4;

    ull acc[4][4];
    {
        const float4 b0 = *(const float4*)&bih[g0 + cg * 8];
        const float4 b1 = *(const float4*)&bih[g0 + cg * 8 + 4];
        ull p0 = pack2(b0.x, b0.y), p1 = pack2(b0.z, b0.w);
        ull p2 = pack2(b1.x, b1.y), p3 = pack2(b1.z, b1.w);
#pragma unroll
        for (int i = 0; i < 4; i++) {
            acc[i][0] = p0; acc[i][1] = p1; acc[i][2] = p2; acc[i][3] = p3;
        }
    }
    __syncthreads();

    for (int kt = 0; kt < VE; kt += 32) {
        {
            const int arow = tid >> 2, kq = tid & 3;
            const float* src = emb + (size_t)tok[arow] * VE + kt + kq * 8;
            const float4 v0 = *(const float4*)(src);
            const float4 v1 = *(const float4*)(src + 4);
            const int kb = kq * 8;
            As[(kb + 0) * 64 + arow] = v0.x; As[(kb + 1) * 64 + arow] = v0.y;
            As[(kb + 2) * 64 + arow] = v0.z; As[(kb + 3) * 64 + arow] = v0.w;
            As[(kb + 4) * 64 + arow] = v1.x; As[(kb + 5) * 64 + arow] = v1.y;
            As[(kb + 6) * 64 + arow] = v1.z; As[(kb + 7) * 64 + arow] = v1.w;
        }
        {
            const int grow = tid >> 1, kh = tid & 1;
            const float* src = Wih + (size_t)(g0 + grow) * VE + kt + kh * 16;
#pragma unroll
            for (int q = 0; q < 4; q++) {
                const float4 v = *(const float4*)(src + q * 4);
                const int kb = kh * 16 + q * 4;
                Bs[(kb + 0) * 128 + grow] = v.x; Bs[(kb + 1) * 128 + grow] = v.y;
                Bs[(kb + 2) * 128 + grow] = v.z; Bs[(kb + 3) * 128 + grow] = v.w;
            }
        }
        __syncthreads();
#pragma unroll
        for (int k = 0; k < 32; k++) {
            const float4 av = *(const float4*)&As[k * 64 + rg * 4];
            const ull pa0 = pack2(av.x, av.x), pa1 = pack2(av.y, av.y);
            const ull pa2 = pack2(av.z, av.z), pa3 = pack2(av.w, av.w);
            const ulonglong2 bA = *(const ulonglong2*)&Bs[k * 128 + cg * 8];
            const ulonglong2 bB = *(const ulonglong2*)&Bs[k * 128 + cg * 8 + 4];
            acc[0][0] = fma2(pa0, bA.x, acc[0][0]); acc[0][1] = fma2(pa0, bA.y, acc[0][1]);
            acc[0][2] = fma2(pa0, bB.x, acc[0][2]); acc[0][3] = fma2(pa0, bB.y, acc[0][3]);
            acc[1][0] = fma2(pa1, bA.x, acc[1][0]); acc[1][1] = fma2(pa1, bA.y, acc[1][1]);
            acc[1][2] = fma2(pa1, bB.x, acc[1][2]); acc[1][3] = fma2(pa1, bB.y, acc[1][3]);
            acc[2][0] = fma2(pa2, bA.x, acc[2][0]); acc[2][1] = fma2(pa2, bA.y, acc[2][1]);
            acc[2][2] = fma2(pa2, bB.x, acc[2][2]); acc[2][3] = fma2(pa2, bB.y, acc[2][3]);
            acc[3][0] = fma2(pa3, bA.x, acc[3][0]); acc[3][1] = fma2(pa3, bA.y, acc[3][1]);
            acc[3][2] = fma2(pa3, bB.x, acc[3][2]); acc[3][3] = fma2(pa3, bB.y, acc[3][3]);
        }
        __syncthreads();
    }

#pragma unroll
    for (int i = 0; i < 4; i++) {
        float o0, o1, o2, o3, o4, o5, o6, o7;
        unpk(acc[i][0], o0, o1); unpk(acc[i][1], o2, o3);
        unpk(acc[i][2], o4, o5); unpk(acc[i][3], o6, o7);
        float* dst = g_gi + (size_t)(s * VB + rg * 4 + i) * G3H + g0 + cg * 8;
        float4 w0; w0.x = o0; w0.y = o1; w0.z = o2; w0.w = o3;
        float4 w1; w1.x = o4; w1.y = o5; w1.z = o6; w1.w = o7;
        *(float4*)(dst) = w0;
        *(float4*)(dst + 4) = w1;
    }
}

// ---------------------------------------------------------------------------
// Kernel B: persistent GRU, k-split mapping.
// thread = (ul:4, bq:16, ks:4). Thread accumulates 3 gate partials over its
// k-quarter for 4 batch rows (bq, +16, +32, +48): 7 LDS per 24 FMA2.
// Each 64-thread ks-group copies & reads ONLY its own quarter buffer
// (2 cp.async half-groups pipelined, named barrier id=1+ks).
// Cross-ks reduction via SMEM part[g][ks][b*4+ul] (conflict-free STS/LDS).
// ---------------------------------------------------------------------------
#define GRU_CTAS 128
#define WPITCH   516
#define QFLOATS  8192                       // quarter = 32 chunks x 64 b x 4
#define PART_OFF (12 * WPITCH + 4 * QFLOATS)
#define GRU_SMEM ((PART_OFF + 3072) * 4)    // 180,416? -> (6192+32768+3072)*4=168128 B

__global__ void __launch_bounds__(256, 1) gru_kernel(const float* __restrict__ Whh,
                                                     const float* __restrict__ bhh) {
    extern __shared__ __align__(16) float dyn[];
    float* ws   = dyn;                       // 12 * WPITCH
    float* part = dyn + PART_OFF;            // 3 * 4 * 256

    const int tid = threadIdx.x;
    const int cta = blockIdx.x;
    const int ul = tid & 3;                  // unit (shared by both mappings)
    const int bq = (tid >> 2) & 15;          // compute: base batch row
    const int ks = tid >> 6;                 // compute: k-quarter
    const int eb = tid >> 2;                 // epilogue batch row
    const int u  = cta * 4 + ul;

    float* hq = dyn + 12 * WPITCH + ks * QFLOATS;
    const int lane64 = tid & 63;

    for (int idx = tid; idx < 12 * VH; idx += 256) {
        const int lr = idx >> 9, k = idx & 511;
        const int g = lr >> 2, uu = lr & 3;
        ws[lr * WPITCH + k] = Whh[(size_t)(g * VH + cta * 4 + uu) * VH + k];
    }
    const float bR = bhh[u], bZ = bhh[VH + u], bN = bhh[2 * VH + u];
    __syncthreads();

    // chunk pointers, pre-offset to this thread's quarter
    const ulonglong2* wR = (const ulonglong2*)&ws[(0 + ul) * WPITCH] + ks * 32;
    const ulonglong2* wZ = (const ulonglong2*)&ws[(4 + ul) * WPITCH] + ks * 32;
    const ulonglong2* wN = (const ulonglong2*)&ws[(8 + ul) * WPITCH] + ks * 32;

    const unsigned hq_s = (unsigned)__cvta_generic_to_shared(hq);

#define CITER(c)                                                            \
    {                                                                       \
        const ulonglong2 r2 = wR[(c)];                                      \
        const ulonglong2 z2 = wZ[(c)];                                      \
        const ulonglong2 n2 = wN[(c)];                                      \
        const float* hb = hq + (c) * 256;                                   \
        const ulonglong2 h0 = *(const ulonglong2*)(hb + bq * 4);            \
        const ulonglong2 h1 = *(const ulonglong2*)(hb + (bq + 16) * 4);     \
        const ulonglong2 hx2 = *(const ulonglong2*)(hb + (bq + 32) * 4);    \
        const ulonglong2 hx3 = *(const ulonglong2*)(hb + (bq + 48) * 4);    \
        aR0 = fma2(h0.x, r2.x, aR0);  aR0 = fma2(h0.y, r2.y, aR0);          \
        aR1 = fma2(h1.x, r2.x, aR1);  aR1 = fma2(h1.y, r2.y, aR1);          \
        aR2 = fma2(hx2.x, r2.x, aR2); aR2 = fma2(hx2.y, r2.y, aR2);         \
        aR3 = fma2(hx3.x, r2.x, aR3); aR3 = fma2(hx3.y, r2.y, aR3);         \
        aZ0 = fma2(h0.x, z2.x, aZ0);  aZ0 = fma2(h0.y, z2.y, aZ0);          \
        aZ1 = fma2(h1.x, z2.x, aZ1);  aZ1 = fma2(h1.y, z2.y, aZ1);          \
        aZ2 = fma2(hx2.x, z2.x, aZ2); aZ2 = fma2(hx2.y, z2.y, aZ2);         \
        aZ3 = fma2(hx3.x, z2.x, aZ3); aZ3 = fma2(hx3.y, z2.y, aZ3);         \
        aN0 = fma2(h0.x, n2.x, aN0);  aN0 = fma2(h0.y, n2.y, aN0);          \
        aN1 = fma2(h1.x, n2.x, aN1);  aN1 = fma2(h1.y, n2.y, aN1);          \
        aN2 = fma2(hx2.x, n2.x, aN2); aN2 = fma2(hx2.y, n2.y, aN2);         \
        aN3 = fma2(hx3.x, n2.x, aN3); aN3 = fma2(hx3.y, n2.y, aN3);         \
    }

    for (int s = 0; s < VS; s++) {
        const float* hf = g_states + (size_t)s * (VB * VH);
        const char* gsrc = (const char*)(hf + ks * QFLOATS);

        // copy own quarter in two pipelined halves (16 x 16B each)
#pragma unroll
        for (int j = 0; j < 16; j++) {
            const int off = (j * 64 + lane64) * 16;
            asm volatile("cp.async.cg.shared.global [%0], [%1], 16;"
                         :: "r"(hq_s + off), "l"(gsrc + off) : "memory");
        }
        asm volatile("cp.async.commit_group;" ::: "memory");
#pragma unroll
        for (int j = 16; j < 32; j++) {
            const int off = (j * 64 + lane64) * 16;
            asm volatile("cp.async.cg.shared.global [%0], [%1], 16;"
                         :: "r"(hq_s + off), "l"(gsrc + off) : "memory");
        }
        asm volatile("cp.async.commit_group;" ::: "memory");

        // early independent loads (consumed only in epilogue)
        const float* gis = g_gi + (size_t)(s * VB + eb) * G3H;
        const float gr = __ldg(gis + u);
        const float gz = __ldg(gis + VH + u);
        const float gn = __ldg(gis + 2 * VH + u);
        const float hp = __ldcg(hf + cta * 256 + tid);

        ull aR0 = 0, aR1 = 0, aR2 = 0, aR3 = 0;
        ull aZ0 = 0, aZ1 = 0, aZ2 = 0, aZ3 = 0;
        ull aN0 = 0, aN1 = 0, aN2 = 0, aN3 = 0;

        asm volatile("cp.async.wait_group 1;" ::: "memory");
        asm volatile("bar.sync %0, 64;" :: "r"(1 + ks) : "memory");
#pragma unroll
        for (int c = 0; c < 16; c++) CITER(c);
        asm volatile("cp.async.wait_group 0;" ::: "memory");
        asm volatile("bar.sync %0, 64;" :: "r"(1 + ks) : "memory");
#pragma unroll
        for (int c = 16; c < 32; c++) CITER(c);

        // store partials: part[(g*4+ks)*256 + b*4 + ul]  (conflict-free)
        {
            float* pR = part + (0 * 4 + ks) * 256 + bq * 4 + ul;
            float* pZ = part + (1 * 4 + ks) * 256 + bq * 4 + ul;
            float* pN = part + (2 * 4 + ks) * 256 + bq * 4 + ul;
            pR[0]  = sum2(aR0); pR[64]  = sum2(aR1); pR[128]  = sum2(aR2); pR[192]  = sum2(aR3);
            pZ[0]  = sum2(aZ0); pZ[64]  = sum2(aZ1); pZ[128]  = sum2(aZ2); pZ[192]  = sum2(aZ3);
            pN[0]  = sum2(aN0); pN[64]  = sum2(aN1); pN[128]  = sum2(aN2); pN[192]  = sum2(aN3);
        }
        __syncthreads();

        // cross-ks reduction + epilogue (thread -> (eb, ul))
        const float dr = part[0 * 256 + tid] + part[1 * 256 + tid]
                       + part[2 * 256 + tid] + part[3 * 256 + tid];
        const float dz = part[4 * 256 + tid] + part[5 * 256 + tid]
                       + part[6 * 256 + tid] + part[7 * 256 + tid];
        const float dn = part[8 * 256 + tid] + part[9 * 256 + tid]
                       + part[10 * 256 + tid] + part[11 * 256 + tid];

        const float r = 1.0f / (1.0f + expf(-(gr + dr + bR)));
        const float z = 1.0f / (1.0f + expf(-(gz + dz + bZ)));
        const float n = tanhf(gn + r * (dn + bN));
        const float hnew = (1.0f - z) * n + z * hp;

        __stcg(g_states + (size_t)(s + 1) * (VB * VH) + cta * 256 + tid, hnew);

        // grid-wide step barrier (proven)
        __syncthreads();
        if (tid == 0) {
            __threadfence();
            const unsigned arrived = atomicAdd(&g_bar_count, 1u);
            if (arrived == GRU_CTAS - 1) {
                atomicExch(&g_bar_count, 0u);
                __threadfence();
                atomicExch(&g_bar_gen, (unsigned)(s + 1));
            } else {
                while (*(volatile unsigned*)&g_bar_gen < (unsigned)(s + 1)) {}
            }
            __threadfence();
        }
        __syncthreads();
    }
#undef CITER
}

// ---------------------------------------------------------------------------
// Kernel C: tag_logits = states @ W_tag^T + b_tag ; preds (proven)
// ---------------------------------------------------------------------------
#define WT_PITCH 68

__global__ void __launch_bounds__(256) tag_kernel(const float* __restrict__ Wtag,
                                                  const float* __restrict__ btag,
                                                  float* __restrict__ out,
                                                  int preds_off, int write_preds) {
    __shared__ __align__(16) float Wt[128 * WT_PITCH];

    const int tid = threadIdx.x;
    const int r = tid >> 2;
    const int tg4 = tid & 3;
    const int m = blockIdx.x * 64 + r;        // m = b*512 + s
    const int bb = m >> 9, s = m & 511;
    const float* st = g_states + (size_t)(s + 1) * (VB * VH) + bb * 4;

    float acc[16];
#pragma unroll
    for (int j = 0; j < 16; j++) acc[j] = btag[tg4 * 16 + j];

    for (int cc = 0; cc < 4; cc++) {
        __syncthreads();
        for (int idx = tid; idx < VT * 128; idx += 256) {
            const int tg = idx >> 7, kk = idx & 127;
            Wt[kk * WT_PITCH + tg] = Wtag[(size_t)tg * VH + cc * 128 + kk];
        }
        __syncthreads();
#pragma unroll 4
        for (int c = 0; c < 32; c++) {
            const float4 a4 = __ldg((const float4*)(st + (size_t)(cc * 32 + c) * 256));
#pragma unroll
            for (int kq = 0; kq < 4; kq++) {
                const float av = (kq == 0) ? a4.x : (kq == 1) ? a4.y : (kq == 2) ? a4.z : a4.w;
                const float4* w4p = (const float4*)&Wt[(c * 4 + kq) * WT_PITCH + tg4 * 16];
                const float4 w0 = w4p[0], w1 = w4p[1], w2 = w4p[2], w3 = w4p[3];
                acc[0]  = fmaf(av, w0.x, acc[0]);  acc[1]  = fmaf(av, w0.y, acc[1]);
                acc[2]  = fmaf(av, w0.z, acc[2]);  acc[3]  = fmaf(av, w0.w, acc[3]);
                acc[4]  = fmaf(av, w1.x, acc[4]);  acc[5]  = fmaf(av, w1.y, acc[5]);
                acc[6]  = fmaf(av, w1.z, acc[6]);  acc[7]  = fmaf(av, w1.w, acc[7]);
                acc[8]  = fmaf(av, w2.x, acc[8]);  acc[9]  = fmaf(av, w2.y, acc[9]);
                acc[10] = fmaf(av, w2.z, acc[10]); acc[11] = fmaf(av, w2.w, acc[11]);
                acc[12] = fmaf(av, w3.x, acc[12]); acc[13] = fmaf(av, w3.y, acc[13]);
                acc[14] = fmaf(av, w3.z, acc[14]); acc[15] = fmaf(av, w3.w, acc[15]);
            }
        }
    }

    {
        float* dst = out + (size_t)m * VT + tg4 * 16;
#pragma unroll
        for (int q = 0; q < 4; q++) {
            float4 v;
            v.x = acc[q * 4]; v.y = acc[q * 4 + 1];
            v.z = acc[q * 4 + 2]; v.w = acc[q * 4 + 3];
            *(float4*)(dst + q * 4) = v;
        }
    }

    if (write_preds) {
        float v = acc[0]; int bi = 0;
#pragma unroll
        for (int j = 1; j < 16; j++) { if (acc[j] > v) { v = acc[j]; bi = j; } }
        bi += tg4 * 16;
#pragma unroll
        for (int off = 2; off >= 1; off >>= 1) {
            const float v2 = __shfl_down_sync(0xFFFFFFFFu, v, off, 4);
            const int i2 = __shfl_down_sync(0xFFFFFFFFu, bi, off, 4);
            if (v2 > v) { v = v2; bi = i2; }
        }
        if (tg4 == 0) {
            const int t = g_tok[bb * VS + s];
            out[preds_off + m] = (t != 0) ? (float)bi : 0.0f;
        }
    }
}

// ---------------------------------------------------------------------------
extern "C" void kernel_launch(void* const* d_in, const int* in_sizes, int n_in,
                              void* d_out, int out_size) {
    const int*   tokens_raw = (const int*)d_in[0];
    const float* emb  = (const float*)d_in[1];
    const float* Wih  = (const float*)d_in[2];
    const float* Whh  = (const float*)d_in[3];
    const float* bih  = (const float*)d_in[4];
    const float* bhh  = (const float*)d_in[5];
    const float* Wtag = (const float*)d_in[6];
    const float* btag = (const float*)d_in[7];
    float* out = (float*)d_out;

    const int logits_n = VB * VS * VT;                 // 2097152
    const int write_preds = (out_size >= logits_n + VB * VS) ? 1 : 0;

    static int smem_set = 0;
    if (!smem_set) {
        cudaFuncSetAttribute(gru_kernel, cudaFuncAttributeMaxDynamicSharedMemorySize, GRU_SMEM);
        smem_set = 1;
    }

    tok_kernel<<<1, 256>>>(tokens_raw);
    init_kernel<<<256, 256>>>(out, out_size);
    gi_kernel<<<dim3(12, 512), 256>>>(emb, Wih, bih);
    gru_kernel<<<GRU_CTAS, 256, GRU_SMEM>>>(Whh, bhh);
    tag_kernel<<<512, 256>>>(Wtag, btag, out, logits_n, write_preds);
}